// round 6
// baseline (speedup 1.0000x reference)
#include <cuda_runtime.h>
#include <cstdint>

// CrfHead: out[b,t,:] = x[b,t,:] + transitions[argmax(x[b,t,:]), :]
// 131072 rows x 256 floats. Register software pipeline: each warp owns 8
// contiguous rows; next row's x-loads are issued BEFORE the current row's
// argmax -> L2 transitions gather -> store tail, so DRAM reads stay in
// flight for ~the whole warp lifetime (R3/R4 duty cycle was ~53%).

#define TAGS 256
#define ROWS (128 * 1024)
#define THREADS 256
#define RPW 8                                   // rows per warp
#define WARPS_TOTAL (ROWS / RPW)                // 16384
#define BLOCKS (WARPS_TOTAL / (THREADS / 32))   // 2048
#define F4_PER_ROW (TAGS / 4)                   // 64

// Monotone float -> uint32 map (total order matches float <; no NaNs in input).
__device__ __forceinline__ unsigned ford(float f) {
    unsigned u = __float_as_uint(f);
    return (u >> 31) ? ~u : (u | 0x80000000u);
}

__global__ __launch_bounds__(THREADS, 6)
void crf_head_kernel(const float4* __restrict__ x,
                     const float* __restrict__ trans,
                     float4* __restrict__ out) {
    const int warp = (blockIdx.x * THREADS + threadIdx.x) >> 5;
    const int lane = threadIdx.x & 31;

    const size_t base = (size_t)warp * RPW * F4_PER_ROW;
    const float4* gx   = x + base;
    float4*       gout = out + base;

    // Prime the pipeline: row 0 loads in flight.
    float4 a = __ldcs(&gx[lane]);
    float4 b = __ldcs(&gx[lane + 32]);

    #pragma unroll
    for (int i = 0; i < RPW; i++) {
        // Issue next row's independent loads FIRST (overlap the tail below).
        float4 na, nb;
        if (i + 1 < RPW) {
            const float4* np = gx + (size_t)(i + 1) * F4_PER_ROW;
            na = __ldcs(&np[lane]);
            nb = __ldcs(&np[lane + 32]);
        }

        // Lane-local argmax over 8 elems; strict > keeps lowest index.
        const int i0 = lane * 4, i1 = (lane + 32) * 4;
        float v = a.x; int idx = i0;
        if (a.y > v) { v = a.y; idx = i0 + 1; }
        if (a.z > v) { v = a.z; idx = i0 + 2; }
        if (a.w > v) { v = a.w; idx = i0 + 3; }
        if (b.x > v) { v = b.x; idx = i1;     }
        if (b.y > v) { v = b.y; idx = i1 + 1; }
        if (b.z > v) { v = b.z; idx = i1 + 2; }
        if (b.w > v) { v = b.w; idx = i1 + 3; }

        // Warp argmax: REDUX.MAX on ordered key, REDUX.MIN on candidate index
        // (exact first-occurrence tie-break; lanes own disjoint index sets).
        const unsigned k = ford(v);
        const unsigned m = __reduce_max_sync(0xFFFFFFFFu, k);
        const unsigned cand = (k == m) ? (unsigned)idx : 0xFFFFu;
        const int best = (int)__reduce_min_sync(0xFFFFFFFFu, cand);

        // transitions row: 256KB total working set, L2-resident.
        const float4* trow = reinterpret_cast<const float4*>(trans + (size_t)best * TAGS);
        const float4 t0 = __ldg(&trow[lane]);
        const float4 t1 = __ldg(&trow[lane + 32]);

        float4* orow = gout + (size_t)i * F4_PER_ROW;
        float4 r;
        r.x = a.x + t0.x; r.y = a.y + t0.y; r.z = a.z + t0.z; r.w = a.w + t0.w;
        __stcs(&orow[lane], r);
        r.x = b.x + t1.x; r.y = b.y + t1.y; r.z = b.z + t1.z; r.w = b.w + t1.w;
        __stcs(&orow[lane + 32], r);

        a = na; b = nb;
    }
}

extern "C" void kernel_launch(void* const* d_in, const int* in_sizes, int n_in,
                              void* d_out, int out_size) {
    const float4* x     = reinterpret_cast<const float4*>(d_in[0]);
    const float*  trans = reinterpret_cast<const float*>(d_in[1]);
    float4*       out   = reinterpret_cast<float4*>(d_out);

    crf_head_kernel<<<BLOCKS, THREADS>>>(x, trans, out);
}

// round 7
// speedup vs baseline: 1.0670x; 1.0670x over previous
#include <cuda_runtime.h>
#include <cstdint>

// CrfHead: out[b,t,:] = x[b,t,:] + transitions[argmax(x[b,t,:]), :]
// 131072 rows x 256 floats. R3 shape (1 row/warp) with cache-policy split:
//   x (268MB stream)      -> __ldcg : L2 only, never allocates in L1
//   transitions (256KB)   -> __ldg  : L1-resident (L1 no longer polluted)
//   out                   -> __stcs
// plus 128-thread blocks @ 100% theoretical occupancy.

#define TAGS 256
#define ROWS (128 * 1024)
#define THREADS 128
#define WARPS_PER_BLOCK (THREADS / 32)
#define BLOCKS (ROWS / WARPS_PER_BLOCK)   // 32768
#define F4_PER_ROW (TAGS / 4)             // 64

// Monotone float -> uint32 map (total order matches float <; no NaNs in input).
__device__ __forceinline__ unsigned ford(float f) {
    unsigned u = __float_as_uint(f);
    return (u >> 31) ? ~u : (u | 0x80000000u);
}

__global__ __launch_bounds__(THREADS, 16)
void crf_head_kernel(const float4* __restrict__ x,
                     const float* __restrict__ trans,
                     float4* __restrict__ out) {
    const int warp = (blockIdx.x * THREADS + threadIdx.x) >> 5;
    const int lane = threadIdx.x & 31;

    const size_t base = (size_t)warp * F4_PER_ROW;

    // Streaming reads: L2-only so L1 stays reserved for transitions.
    const float4 a = __ldcg(&x[base + lane]);
    const float4 b = __ldcg(&x[base + lane + 32]);

    // Lane-local argmax over 8 elems; strict > keeps lowest index.
    const int i0 = lane * 4, i1 = (lane + 32) * 4;
    float v = a.x; int idx = i0;
    if (a.y > v) { v = a.y; idx = i0 + 1; }
    if (a.z > v) { v = a.z; idx = i0 + 2; }
    if (a.w > v) { v = a.w; idx = i0 + 3; }
    if (b.x > v) { v = b.x; idx = i1;     }
    if (b.y > v) { v = b.y; idx = i1 + 1; }
    if (b.z > v) { v = b.z; idx = i1 + 2; }
    if (b.w > v) { v = b.w; idx = i1 + 3; }

    // Warp argmax: REDUX.MAX on ordered key, REDUX.MIN on candidate index
    // (exact first-occurrence tie-break; lanes own disjoint index sets).
    const unsigned k = ford(v);
    const unsigned m = __reduce_max_sync(0xFFFFFFFFu, k);
    const unsigned cand = (k == m) ? (unsigned)idx : 0xFFFFu;
    const int best = (int)__reduce_min_sync(0xFFFFFFFFu, cand);

    // transitions row: 256KB working set, now L1-resident (ld.global.nc).
    const float4* trow = reinterpret_cast<const float4*>(trans + (size_t)best * TAGS);
    const float4 t0 = __ldg(&trow[lane]);
    const float4 t1 = __ldg(&trow[lane + 32]);

    float4 r;
    r.x = a.x + t0.x; r.y = a.y + t0.y; r.z = a.z + t0.z; r.w = a.w + t0.w;
    __stcs(&out[base + lane], r);
    r.x = b.x + t1.x; r.y = b.y + t1.y; r.z = b.z + t1.z; r.w = b.w + t1.w;
    __stcs(&out[base + lane + 32], r);
}

extern "C" void kernel_launch(void* const* d_in, const int* in_sizes, int n_in,
                              void* d_out, int out_size) {
    const float4* x     = reinterpret_cast<const float4*>(d_in[0]);
    const float*  trans = reinterpret_cast<const float*>(d_in[1]);
    float4*       out   = reinterpret_cast<float4*>(d_out);

    crf_head_kernel<<<BLOCKS, THREADS>>>(x, trans, out);
}